// round 7
// baseline (speedup 1.0000x reference)
#include <cuda_runtime.h>
#include <cuda_fp16.h>
#include <cstdint>
#include <cmath>

// ---------------------------------------------------------------------------
// GraphSageLayer: B=4, N=4096, D_IN=128, REP=128, D_OUT=128
//
//  conv_proj (1 launch): adjh = fp16(adj*4096)  +  3 ELU projections
//  agg_both  (1 launch, z=2): upd[:,0:128]   = (adjh @ in_rep)/4096
//                             upd[:,256:384] = (adj^T @ out_rep)/4096 (as
//                             out_rep^T-major product, smem-transposed epi)
//  final     : out = tanh(upd @ W_upd^T + b_upd)
// ---------------------------------------------------------------------------

__device__ __half g_adjh   [4l * 4096 * 4096];  // 134 MB
__device__ __half g_in_rep [4l * 4096 * 128];
__device__ __half g_out_rep[4l * 4096 * 128];
__device__ float  g_upd    [4l * 4096 * 384];

__device__ __forceinline__ uint32_t pack2(float a, float b) {
    uint32_t r;
    asm("cvt.rn.f16x2.f32 %0, %1, %2;" : "=r"(r) : "f"(b), "f"(a));
    return r;
}
__device__ __forceinline__ void cp16(uint32_t dst, const void* src) {
    asm volatile("cp.async.cg.shared.global [%0], [%1], 16;" :: "r"(dst), "l"(src));
}
__device__ __forceinline__ void cp_commit() {
    asm volatile("cp.async.commit_group;");
}
__device__ __forceinline__ void cp_wait2() {
    asm volatile("cp.async.wait_group 2;");
}
__device__ __forceinline__ void ldsm4(uint32_t* r, uint32_t a) {
    asm volatile("ldmatrix.sync.aligned.m8n8.x4.shared.b16 {%0,%1,%2,%3}, [%4];"
        : "=r"(r[0]), "=r"(r[1]), "=r"(r[2]), "=r"(r[3]) : "r"(a));
}
__device__ __forceinline__ void ldsm4t(uint32_t* r, uint32_t a) {
    asm volatile("ldmatrix.sync.aligned.m8n8.x4.trans.shared.b16 {%0,%1,%2,%3}, [%4];"
        : "=r"(r[0]), "=r"(r[1]), "=r"(r[2]), "=r"(r[3]) : "r"(a));
}
__device__ __forceinline__ void mma16816(float* c, const uint32_t* a,
                                         uint32_t b0, uint32_t b1) {
    asm volatile(
        "mma.sync.aligned.m16n8k16.row.col.f32.f16.f16.f32 "
        "{%0,%1,%2,%3}, {%4,%5,%6,%7}, {%8,%9}, {%0,%1,%2,%3};\n"
        : "+f"(c[0]), "+f"(c[1]), "+f"(c[2]), "+f"(c[3])
        : "r"(a[0]), "r"(a[1]), "r"(a[2]), "r"(a[3]), "r"(b0), "r"(b1));
}

// ===========================================================================
// Aggregation body (same proven 4-stage cp.async + ldmatrix loop as R6)
//  OUTT=false: D[m,v] = sum_k adjh[m0+m][k] * rep[k][v]   -> upd[:,0:128]
//  OUTT=true : D[v,j] = sum_k rep[k][v] * adjh[k][n0+j]   -> upd[:,256:384]^T
// ===========================================================================
template<bool OUTT>
__device__ __forceinline__ void agg_body(
    const __half* __restrict__ adjh, const __half* __restrict__ rep,
    float* __restrict__ upd, char* smem)
{
    const int tid  = threadIdx.x;
    const int lane = tid & 31;
    const int warp = tid >> 5;
    const int wm   = warp >> 2;   // 0..1 (m 64 each)
    const int wn   = warp & 3;    // 0..3 (n 32 each)
    const int g    = lane >> 2;
    const int t    = lane & 3;
    const int tile0 = blockIdx.x * 128;   // m0 (in) or n0 (outT)
    const long b   = blockIdx.y;

    const __half* adjB = adjh + b * (4096l * 4096);
    const __half* repB = rep  + b * (4096l * 128);
    float*        updB = upd  + b * (4096l * 384);

    const uint32_t smBase = (uint32_t)__cvta_generic_to_shared(smem);
    constexpr int STAGE = OUTT ? 17408 : 18944;   // bytes per stage
    constexpr int AOFF  = OUTT ? 8704  : 10240;   // B offset within stage

    float acc[4][4][4];
    #pragma unroll
    for (int i = 0; i < 4; i++)
        #pragma unroll
        for (int j = 0; j < 4; j++)
            #pragma unroll
            for (int l = 0; l < 4; l++) acc[i][j][l] = 0.f;

    auto cpTiles = [&](int st, int k0) {
        const uint32_t sA = smBase + st * STAGE;
        const uint32_t sB = sA + AOFF;
        if (!OUTT) {
            #pragma unroll
            for (int i = 0; i < 2; i++) {
                const int c = tid + i * 256, row = c >> 2, kc = c & 3;
                cp16(sA + row * 80 + kc * 16,
                     adjB + (long)(tile0 + row) * 4096 + k0 + kc * 8);
            }
            #pragma unroll
            for (int i = 0; i < 2; i++) {
                const int c = tid + i * 256, k = c >> 4, nc = c & 15;
                cp16(sB + k * 272 + nc * 16,
                     repB + (long)(k0 + k) * 128 + nc * 8);
            }
        } else {
            #pragma unroll
            for (int i = 0; i < 2; i++) {
                const int c = tid + i * 256, k = c >> 4, nc = c & 15;
                cp16(sA + k * 272 + nc * 16,
                     repB + (long)(k0 + k) * 128 + nc * 8);
                cp16(sB + k * 272 + nc * 16,
                     adjB + (long)(k0 + k) * 4096 + tile0 + nc * 8);
            }
        }
    };

    auto compute = [&](int st) {
        const uint32_t sA = smBase + st * STAGE;
        const uint32_t sB = sA + AOFF;
        #pragma unroll
        for (int ks = 0; ks < 2; ks++) {
            uint32_t aF[4][4], bF[2][4];
            #pragma unroll
            for (int mt = 0; mt < 4; mt++) {
                if (!OUTT) {
                    ldsm4(aF[mt], sA + (wm * 64 + mt * 16 + (lane & 15)) * 80
                                     + ((lane >> 4) + 2 * ks) * 16);
                } else {
                    ldsm4t(aF[mt], sA + ((lane & 7) + (lane >> 4) * 8 + 16 * ks) * 272
                                      + (wm * 64 + mt * 16 + ((lane >> 3) & 1) * 8) * 2);
                }
            }
            #pragma unroll
            for (int nt = 0; nt < 2; nt++)
                ldsm4t(bF[nt], sB + ((lane & 15) + 16 * ks) * 272
                                  + wn * 64 + nt * 32 + (lane >> 4) * 16);
            #pragma unroll
            for (int mt = 0; mt < 4; mt++)
                #pragma unroll
                for (int n8 = 0; n8 < 4; n8++)
                    mma16816(acc[mt][n8], aF[mt],
                             bF[n8 >> 1][(n8 & 1) * 2], bF[n8 >> 1][(n8 & 1) * 2 + 1]);
        }
    };

    #pragma unroll
    for (int s = 0; s < 3; s++) { cpTiles(s, s * 32); cp_commit(); }

    #pragma unroll 1
    for (int kt = 0; kt < 128; kt++) {
        cp_wait2();
        __syncthreads();
        const int nx = kt + 3;
        if (nx < 128) cpTiles(nx & 3, nx * 32);
        cp_commit();
        compute(kt & 3);
    }

    const float s = 1.f / 4096.f;
    if (!OUTT) {
        #pragma unroll
        for (int mt = 0; mt < 4; mt++)
            #pragma unroll
            for (int n8 = 0; n8 < 4; n8++) {
                const int row = tile0 + wm * 64 + mt * 16 + g;
                const int col = wn * 32 + n8 * 8 + 2 * t;
                *(float2*)&updB[(long)row * 384 + col] =
                    make_float2(acc[mt][n8][0] * s, acc[mt][n8][1] * s);
                *(float2*)&updB[(long)(row + 8) * 384 + col] =
                    make_float2(acc[mt][n8][2] * s, acc[mt][n8][3] * s);
            }
    } else {
        __syncthreads();
        float* fsm = (float*)smem;   // [v][132] = 67584 B <= 75776 B alloc
        #pragma unroll
        for (int mt = 0; mt < 4; mt++)
            #pragma unroll
            for (int n8 = 0; n8 < 4; n8++) {
                const int v = wm * 64 + mt * 16 + g;
                const int j = wn * 32 + n8 * 8 + 2 * t;
                fsm[v * 132 + j]           = acc[mt][n8][0] * s;
                fsm[v * 132 + j + 1]       = acc[mt][n8][1] * s;
                fsm[(v + 8) * 132 + j]     = acc[mt][n8][2] * s;
                fsm[(v + 8) * 132 + j + 1] = acc[mt][n8][3] * s;
            }
        __syncthreads();
        const int j  = tid >> 1;
        const int vb = (tid & 1) * 64;
        float* dst = &updB[(long)(tile0 + j) * 384 + 256 + vb];
        #pragma unroll
        for (int i = 0; i < 16; i++) {
            const int v = vb + i * 4;
            ((float4*)dst)[i] = make_float4(
                fsm[v * 132 + j],       fsm[(v + 1) * 132 + j],
                fsm[(v + 2) * 132 + j], fsm[(v + 3) * 132 + j]);
        }
    }
}

// Both aggregations in one launch: grid (32, 4, 2) -> single wave, 2 CTA/SM.
__global__ __launch_bounds__(256, 2)
void agg_both(const __half* __restrict__ adjh,
              const __half* __restrict__ in_rep,
              const __half* __restrict__ out_rep,
              float* __restrict__ upd)
{
    extern __shared__ char smem[];
    if (blockIdx.z == 0) agg_body<false>(adjh, in_rep,  upd, smem);
    else                 agg_body<true >(adjh, out_rep, upd, smem);
}

// ===========================================================================
// mma.sync fp16 GEMM for proj / final (small K): CTA 64x128, BK=32.
// ===========================================================================
#define AROW 20
#define BROW 136
enum { EPI_ELU = 1, EPI_TANH = 2 };

template<int EPI, bool HOUT>
__device__ __forceinline__ void gemm_core(
    const float* __restrict__ Af, int lda,
    const float* __restrict__ Bf, int ldb,     // B: NxK row-major (TN)
    const float* __restrict__ bias,
    void* __restrict__ Dv, int ldd, int dOff,
    int K, int m0)
{
    __shared__ uint32_t As[2][64][AROW];
    __shared__ uint32_t Bs[2][16][BROW];

    const int tid  = threadIdx.x;
    const int lane = tid & 31;
    const int warp = tid >> 5;
    const int wm   = warp >> 2;
    const int wn   = warp & 3;
    const int g    = lane >> 2;
    const int t    = lane & 3;

    float acc[2][4][4];
    #pragma unroll
    for (int i = 0; i < 2; i++)
        #pragma unroll
        for (int j = 0; j < 4; j++)
            #pragma unroll
            for (int l = 0; l < 4; l++) acc[i][j][l] = 0.f;

    const int m_a = tid >> 2, q_a = tid & 3;
    const int kkw = tid & 15, nb = (tid >> 4) * 8;

    float fa[8];
    float2 rbf[8];

    auto loadRegs = [&](int k0) {
        const float4* p = (const float4*)(Af + (long)(m0 + m_a) * lda + k0 + 8 * q_a);
        float4 v0 = p[0], v1 = p[1];
        fa[0] = v0.x; fa[1] = v0.y; fa[2] = v0.z; fa[3] = v0.w;
        fa[4] = v1.x; fa[5] = v1.y; fa[6] = v1.z; fa[7] = v1.w;
        #pragma unroll
        for (int i = 0; i < 8; i++)
            rbf[i] = *(const float2*)(Bf + (long)(nb + i) * ldb + k0 + 2 * kkw);
    };
    auto stsRegs = [&](int buf) {
        uint32_t w[4];
        #pragma unroll
        for (int i = 0; i < 4; i++) w[i] = pack2(fa[2 * i], fa[2 * i + 1]);
        *(uint4*)&As[buf][m_a][4 * q_a] = make_uint4(w[0], w[1], w[2], w[3]);
        uint32_t v[8];
        #pragma unroll
        for (int i = 0; i < 8; i++) v[i] = pack2(rbf[i].x, rbf[i].y);
        *(uint4*)&Bs[buf][kkw][nb]     = make_uint4(v[0], v[1], v[2], v[3]);
        *(uint4*)&Bs[buf][kkw][nb + 4] = make_uint4(v[4], v[5], v[6], v[7]);
    };
    auto compute = [&](int buf) {
        #pragma unroll
        for (int ks = 0; ks < 2; ks++) {
            const int k8 = ks * 8;
            uint32_t af[2][4];
            #pragma unroll
            for (int mt = 0; mt < 2; mt++) {
                const int mr = wm * 32 + mt * 16 + g;
                af[mt][0] = As[buf][mr][k8 + t];
                af[mt][1] = As[buf][mr + 8][k8 + t];
                af[mt][2] = As[buf][mr][k8 + t + 4];
                af[mt][3] = As[buf][mr + 8][k8 + t + 4];
            }
            #pragma unroll
            for (int nt = 0; nt < 4; nt++) {
                const int nc = wn * 32 + nt * 8 + g;
                mma16816(acc[0][nt], af[0], Bs[buf][k8 + t][nc], Bs[buf][k8 + t + 4][nc]);
                mma16816(acc[1][nt], af[1], Bs[buf][k8 + t][nc], Bs[buf][k8 + t + 4][nc]);
            }
        }
    };

    const int nk = K / 32;
    loadRegs(0);
    int buf = 0;
    for (int kt = 0; kt < nk; kt++) {
        stsRegs(buf);
        __syncthreads();
        if (kt + 1 < nk) loadRegs((kt + 1) * 32);
        compute(buf);
        buf ^= 1;
    }

    #pragma unroll
    for (int mt = 0; mt < 2; mt++) {
        #pragma unroll
        for (int nt = 0; nt < 4; nt++) {
            const int row = m0 + wm * 32 + mt * 16 + g;
            const int col = wn * 32 + nt * 8 + 2 * t;
            const float b0 = __ldg(bias + col);
            const float b1 = __ldg(bias + col + 1);
            float x0 = acc[mt][nt][0] + b0, x1 = acc[mt][nt][1] + b1;
            float x2 = acc[mt][nt][2] + b0, x3 = acc[mt][nt][3] + b1;
            if (EPI == EPI_ELU) {
                x0 = x0 > 0.f ? x0 : expm1f(x0);
                x1 = x1 > 0.f ? x1 : expm1f(x1);
                x2 = x2 > 0.f ? x2 : expm1f(x2);
                x3 = x3 > 0.f ? x3 : expm1f(x3);
            } else {
                x0 = tanhf(x0); x1 = tanhf(x1);
                x2 = tanhf(x2); x3 = tanhf(x3);
            }
            if (HOUT) {
                __half* Dh = (__half*)Dv;
                *(uint32_t*)&Dh[(long)row       * ldd + dOff + col] = pack2(x0, x1);
                *(uint32_t*)&Dh[(long)(row + 8) * ldd + dOff + col] = pack2(x2, x3);
            } else {
                float* Df = (float*)Dv;
                *(float2*)&Df[(long)row       * ldd + dOff + col] = make_float2(x0, x1);
                *(float2*)&Df[(long)(row + 8) * ldd + dOff + col] = make_float2(x2, x3);
            }
        }
    }
}

// ===========================================================================
// Merged convert + proj3 launch:
//   blocks [0, 32768)        : adjh = fp16(adj * 4096), 8 elems/thread
//   blocks [32768, 32768+768): 3 ELU projections (256 blocks each)
// ===========================================================================
#define CONV_BLOCKS 32768

__global__ __launch_bounds__(256, 2)
void conv_proj(const float* __restrict__ adj, __half* __restrict__ adjh,
               const float* __restrict__ nodes,
               const float* __restrict__ W_in,   const float* __restrict__ b_in,
               const float* __restrict__ W_node, const float* __restrict__ b_node,
               const float* __restrict__ W_out,  const float* __restrict__ b_out,
               __half* __restrict__ in_rep, __half* __restrict__ out_rep,
               float* __restrict__ upd)
{
    if (blockIdx.x < CONV_BLOCKS) {
        const long i = (long)blockIdx.x * 256 + threadIdx.x;
        const float4* src = (const float4*)adj + i * 2;
        float4 a = src[0], b = src[1];
        uint4 o;
        o.x = pack2(a.x * 4096.f, a.y * 4096.f);
        o.y = pack2(a.z * 4096.f, a.w * 4096.f);
        o.z = pack2(b.x * 4096.f, b.y * 4096.f);
        o.w = pack2(b.z * 4096.f, b.w * 4096.f);
        ((uint4*)adjh)[i] = o;
    } else {
        const int bx = blockIdx.x - CONV_BLOCKS;   // 0..767
        const int z  = bx >> 8;
        const int m0 = (bx & 255) * 64;
        if (z == 0)
            gemm_core<EPI_ELU, true >(nodes, 128, W_in,   128, b_in,   in_rep,  128, 0,   128, m0);
        else if (z == 1)
            gemm_core<EPI_ELU, false>(nodes, 128, W_node, 128, b_node, upd,     384, 128, 128, m0);
        else
            gemm_core<EPI_ELU, true >(nodes, 128, W_out,  128, b_out,  out_rep, 128, 0,   128, m0);
    }
}

__global__ __launch_bounds__(256, 2)
void final_kernel(const float* __restrict__ upd, const float* __restrict__ W,
                  const float* __restrict__ b, float* __restrict__ out)
{
    gemm_core<EPI_TANH, false>(upd, 384, W, 384, b, out, 128, 0, 384, blockIdx.x * 64);
}

// ===========================================================================
extern "C" void kernel_launch(void* const* d_in, const int* in_sizes, int n_in,
                              void* d_out, int out_size)
{
    const float* nodes  = (const float*)d_in[0];
    const float* adj    = (const float*)d_in[1];
    const float* W_in   = (const float*)d_in[2];
    const float* b_in   = (const float*)d_in[3];
    const float* W_out  = (const float*)d_in[4];
    const float* b_out  = (const float*)d_in[5];
    const float* W_node = (const float*)d_in[6];
    const float* b_node = (const float*)d_in[7];
    const float* W_upd  = (const float*)d_in[8];
    const float* b_upd  = (const float*)d_in[9];
    float* out = (float*)d_out;

    __half *adjh, *in_rep, *out_rep;
    float *upd;
    cudaGetSymbolAddress((void**)&adjh,    g_adjh);
    cudaGetSymbolAddress((void**)&in_rep,  g_in_rep);
    cudaGetSymbolAddress((void**)&out_rep, g_out_rep);
    cudaGetSymbolAddress((void**)&upd,     g_upd);

    const int SMEM_AGG = 4 * 18944;   // 75776: covers 4-stage (both) + transpose buf
    cudaFuncSetAttribute(agg_both,
                         cudaFuncAttributeMaxDynamicSharedMemorySize, SMEM_AGG);

    // 0+1) adjh conversion + three ELU projections, one launch
    conv_proj<<<CONV_BLOCKS + 768, 256>>>(adj, adjh, nodes,
                                          W_in, b_in, W_node, b_node,
                                          W_out, b_out, in_rep, out_rep, upd);

    // 2+3) both aggregations, one launch (single wave, 2 CTA/SM)
    agg_both<<<dim3(32, 4, 2), 256, SMEM_AGG>>>(adjh, in_rep, out_rep, upd);

    // 4) out = tanh(upd @ W_upd^T + b_upd)
    final_kernel<<<256, 256>>>(upd, W_upd, b_upd, out);
}

// round 8
// speedup vs baseline: 1.2545x; 1.2545x over previous
#include <cuda_runtime.h>
#include <cuda_fp16.h>
#include <cstdint>
#include <cmath>

// ---------------------------------------------------------------------------
// GraphSageLayer: B=4, N=4096, D_IN=128, REP=128, D_OUT=128
//
//  convert  : adjh = fp16(adj * 4096)        (lean streaming kernel)
//  proj3    : in_rep/out_rep = ELU(nodes@W^T+b) fp16; node_rep->upd fp32
//  agg_both (1 launch, z=2): upd[:,0:128]   = (adjh @ in_rep)/4096
//                            upd[:,256:384] = (adj^T @ out_rep)/4096
//  final    : out = tanh(upd @ W_upd^T + b_upd)
// ---------------------------------------------------------------------------

__device__ __half g_adjh   [4l * 4096 * 4096];  // 134 MB
__device__ __half g_in_rep [4l * 4096 * 128];
__device__ __half g_out_rep[4l * 4096 * 128];
__device__ float  g_upd    [4l * 4096 * 384];

__device__ __forceinline__ uint32_t pack2(float a, float b) {
    uint32_t r;
    asm("cvt.rn.f16x2.f32 %0, %1, %2;" : "=r"(r) : "f"(b), "f"(a));
    return r;
}
__device__ __forceinline__ void cp16(uint32_t dst, const void* src) {
    asm volatile("cp.async.cg.shared.global [%0], [%1], 16;" :: "r"(dst), "l"(src));
}
__device__ __forceinline__ void cp_commit() {
    asm volatile("cp.async.commit_group;");
}
__device__ __forceinline__ void cp_wait2() {
    asm volatile("cp.async.wait_group 2;");
}
__device__ __forceinline__ void ldsm4(uint32_t* r, uint32_t a) {
    asm volatile("ldmatrix.sync.aligned.m8n8.x4.shared.b16 {%0,%1,%2,%3}, [%4];"
        : "=r"(r[0]), "=r"(r[1]), "=r"(r[2]), "=r"(r[3]) : "r"(a));
}
__device__ __forceinline__ void ldsm4t(uint32_t* r, uint32_t a) {
    asm volatile("ldmatrix.sync.aligned.m8n8.x4.trans.shared.b16 {%0,%1,%2,%3}, [%4];"
        : "=r"(r[0]), "=r"(r[1]), "=r"(r[2]), "=r"(r[3]) : "r"(a));
}
__device__ __forceinline__ void mma16816(float* c, const uint32_t* a,
                                         uint32_t b0, uint32_t b1) {
    asm volatile(
        "mma.sync.aligned.m16n8k16.row.col.f32.f16.f16.f32 "
        "{%0,%1,%2,%3}, {%4,%5,%6,%7}, {%8,%9}, {%0,%1,%2,%3};\n"
        : "+f"(c[0]), "+f"(c[1]), "+f"(c[2]), "+f"(c[3])
        : "r"(a[0]), "r"(a[1]), "r"(a[2]), "r"(a[3]), "r"(b0), "r"(b1));
}

// ===========================================================================
// convert: adjh = fp16(adj * 4096), 8 elems/thread, streaming loads.
// Lean: no smem, few regs -> full occupancy, DRAM-bound.
// ===========================================================================
__global__ __launch_bounds__(1024)
void convert_adj(const float* __restrict__ adj, __half* __restrict__ adjh)
{
    const long i = (long)blockIdx.x * blockDim.x + threadIdx.x;
    const float4* src = (const float4*)adj + i * 2;
    float4 a = __ldcs(src);
    float4 b = __ldcs(src + 1);
    uint4 o;
    o.x = pack2(a.x * 4096.f, a.y * 4096.f);
    o.y = pack2(a.z * 4096.f, a.w * 4096.f);
    o.z = pack2(b.x * 4096.f, b.y * 4096.f);
    o.w = pack2(b.z * 4096.f, b.w * 4096.f);
    ((uint4*)adjh)[i] = o;
}

// ===========================================================================
// Aggregation body (proven 4-stage cp.async + ldmatrix loop)
//  OUTT=false: D[m,v] = sum_k adjh[m0+m][k] * rep[k][v]   -> upd[:,0:128]
//  OUTT=true : D[v,j] = sum_k rep[k][v] * adjh[k][n0+j]   -> upd[:,256:384]^T
// ===========================================================================
template<bool OUTT>
__device__ __forceinline__ void agg_body(
    const __half* __restrict__ adjh, const __half* __restrict__ rep,
    float* __restrict__ upd, char* smem)
{
    const int tid  = threadIdx.x;
    const int lane = tid & 31;
    const int warp = tid >> 5;
    const int wm   = warp >> 2;   // 0..1 (m 64 each)
    const int wn   = warp & 3;    // 0..3 (n 32 each)
    const int g    = lane >> 2;
    const int t    = lane & 3;
    const int tile0 = blockIdx.x * 128;   // m0 (in) or n0 (outT)
    const long b   = blockIdx.y;

    const __half* adjB = adjh + b * (4096l * 4096);
    const __half* repB = rep  + b * (4096l * 128);
    float*        updB = upd  + b * (4096l * 384);

    const uint32_t smBase = (uint32_t)__cvta_generic_to_shared(smem);
    constexpr int STAGE = OUTT ? 17408 : 18944;   // bytes per stage
    constexpr int AOFF  = OUTT ? 8704  : 10240;   // B offset within stage

    float acc[4][4][4];
    #pragma unroll
    for (int i = 0; i < 4; i++)
        #pragma unroll
        for (int j = 0; j < 4; j++)
            #pragma unroll
            for (int l = 0; l < 4; l++) acc[i][j][l] = 0.f;

    auto cpTiles = [&](int st, int k0) {
        const uint32_t sA = smBase + st * STAGE;
        const uint32_t sB = sA + AOFF;
        if (!OUTT) {
            #pragma unroll
            for (int i = 0; i < 2; i++) {
                const int c = tid + i * 256, row = c >> 2, kc = c & 3;
                cp16(sA + row * 80 + kc * 16,
                     adjB + (long)(tile0 + row) * 4096 + k0 + kc * 8);
            }
            #pragma unroll
            for (int i = 0; i < 2; i++) {
                const int c = tid + i * 256, k = c >> 4, nc = c & 15;
                cp16(sB + k * 272 + nc * 16,
                     repB + (long)(k0 + k) * 128 + nc * 8);
            }
        } else {
            #pragma unroll
            for (int i = 0; i < 2; i++) {
                const int c = tid + i * 256, k = c >> 4, nc = c & 15;
                cp16(sA + k * 272 + nc * 16,
                     repB + (long)(k0 + k) * 128 + nc * 8);
                cp16(sB + k * 272 + nc * 16,
                     adjB + (long)(k0 + k) * 4096 + tile0 + nc * 8);
            }
        }
    };

    auto compute = [&](int st) {
        const uint32_t sA = smBase + st * STAGE;
        const uint32_t sB = sA + AOFF;
        #pragma unroll
        for (int ks = 0; ks < 2; ks++) {
            uint32_t aF[4][4], bF[2][4];
            #pragma unroll
            for (int mt = 0; mt < 4; mt++) {
                if (!OUTT) {
                    ldsm4(aF[mt], sA + (wm * 64 + mt * 16 + (lane & 15)) * 80
                                     + ((lane >> 4) + 2 * ks) * 16);
                } else {
                    ldsm4t(aF[mt], sA + ((lane & 7) + (lane >> 4) * 8 + 16 * ks) * 272
                                      + (wm * 64 + mt * 16 + ((lane >> 3) & 1) * 8) * 2);
                }
            }
            #pragma unroll
            for (int nt = 0; nt < 2; nt++)
                ldsm4t(bF[nt], sB + ((lane & 15) + 16 * ks) * 272
                                  + wn * 64 + nt * 32 + (lane >> 4) * 16);
            #pragma unroll
            for (int mt = 0; mt < 4; mt++)
                #pragma unroll
                for (int n8 = 0; n8 < 4; n8++)
                    mma16816(acc[mt][n8], aF[mt],
                             bF[n8 >> 1][(n8 & 1) * 2], bF[n8 >> 1][(n8 & 1) * 2 + 1]);
        }
    };

    #pragma unroll
    for (int s = 0; s < 3; s++) { cpTiles(s, s * 32); cp_commit(); }

    #pragma unroll 1
    for (int kt = 0; kt < 128; kt++) {
        cp_wait2();
        __syncthreads();
        const int nx = kt + 3;
        if (nx < 128) cpTiles(nx & 3, nx * 32);
        cp_commit();
        compute(kt & 3);
    }

    const float s = 1.f / 4096.f;
    if (!OUTT) {
        #pragma unroll
        for (int mt = 0; mt < 4; mt++)
            #pragma unroll
            for (int n8 = 0; n8 < 4; n8++) {
                const int row = tile0 + wm * 64 + mt * 16 + g;
                const int col = wn * 32 + n8 * 8 + 2 * t;
                *(float2*)&updB[(long)row * 384 + col] =
                    make_float2(acc[mt][n8][0] * s, acc[mt][n8][1] * s);
                *(float2*)&updB[(long)(row + 8) * 384 + col] =
                    make_float2(acc[mt][n8][2] * s, acc[mt][n8][3] * s);
            }
    } else {
        __syncthreads();
        float* fsm = (float*)smem;   // [v][132] = 67584 B <= 75776 B alloc
        #pragma unroll
        for (int mt = 0; mt < 4; mt++)
            #pragma unroll
            for (int n8 = 0; n8 < 4; n8++) {
                const int v = wm * 64 + mt * 16 + g;
                const int j = wn * 32 + n8 * 8 + 2 * t;
                fsm[v * 132 + j]           = acc[mt][n8][0] * s;
                fsm[v * 132 + j + 1]       = acc[mt][n8][1] * s;
                fsm[(v + 8) * 132 + j]     = acc[mt][n8][2] * s;
                fsm[(v + 8) * 132 + j + 1] = acc[mt][n8][3] * s;
            }
        __syncthreads();
        const int j  = tid >> 1;
        const int vb = (tid & 1) * 64;
        float* dst = &updB[(long)(tile0 + j) * 384 + 256 + vb];
        #pragma unroll
        for (int i = 0; i < 16; i++) {
            const int v = vb + i * 4;
            ((float4*)dst)[i] = make_float4(
                fsm[v * 132 + j],       fsm[(v + 1) * 132 + j],
                fsm[(v + 2) * 132 + j], fsm[(v + 3) * 132 + j]);
        }
    }
}

// Both aggregations in one launch: grid (32, 4, 2) -> single wave, 2 CTA/SM.
__global__ __launch_bounds__(256, 2)
void agg_both(const __half* __restrict__ adjh,
              const __half* __restrict__ in_rep,
              const __half* __restrict__ out_rep,
              float* __restrict__ upd)
{
    extern __shared__ char smem[];
    if (blockIdx.z == 0) agg_body<false>(adjh, in_rep,  upd, smem);
    else                 agg_body<true >(adjh, out_rep, upd, smem);
}

// ===========================================================================
// mma.sync fp16 GEMM for proj / final (small K): CTA 64x128, BK=32.
// ===========================================================================
#define AROW 20
#define BROW 136
enum { EPI_ELU = 1, EPI_TANH = 2 };

template<int EPI, bool HOUT>
__device__ __forceinline__ void gemm_core(
    const float* __restrict__ Af, int lda,
    const float* __restrict__ Bf, int ldb,     // B: NxK row-major (TN)
    const float* __restrict__ bias,
    void* __restrict__ Dv, int ldd, int dOff,
    int K, int m0)
{
    __shared__ uint32_t As[2][64][AROW];
    __shared__ uint32_t Bs[2][16][BROW];

    const int tid  = threadIdx.x;
    const int lane = tid & 31;
    const int warp = tid >> 5;
    const int wm   = warp >> 2;
    const int wn   = warp & 3;
    const int g    = lane >> 2;
    const int t    = lane & 3;

    float acc[2][4][4];
    #pragma unroll
    for (int i = 0; i < 2; i++)
        #pragma unroll
        for (int j = 0; j < 4; j++)
            #pragma unroll
            for (int l = 0; l < 4; l++) acc[i][j][l] = 0.f;

    const int m_a = tid >> 2, q_a = tid & 3;
    const int kkw = tid & 15, nb = (tid >> 4) * 8;

    float fa[8];
    float2 rbf[8];

    auto loadRegs = [&](int k0) {
        const float4* p = (const float4*)(Af + (long)(m0 + m_a) * lda + k0 + 8 * q_a);
        float4 v0 = p[0], v1 = p[1];
        fa[0] = v0.x; fa[1] = v0.y; fa[2] = v0.z; fa[3] = v0.w;
        fa[4] = v1.x; fa[5] = v1.y; fa[6] = v1.z; fa[7] = v1.w;
        #pragma unroll
        for (int i = 0; i < 8; i++)
            rbf[i] = *(const float2*)(Bf + (long)(nb + i) * ldb + k0 + 2 * kkw);
    };
    auto stsRegs = [&](int buf) {
        uint32_t w[4];
        #pragma unroll
        for (int i = 0; i < 4; i++) w[i] = pack2(fa[2 * i], fa[2 * i + 1]);
        *(uint4*)&As[buf][m_a][4 * q_a] = make_uint4(w[0], w[1], w[2], w[3]);
        uint32_t v[8];
        #pragma unroll
        for (int i = 0; i < 8; i++) v[i] = pack2(rbf[i].x, rbf[i].y);
        *(uint4*)&Bs[buf][kkw][nb]     = make_uint4(v[0], v[1], v[2], v[3]);
        *(uint4*)&Bs[buf][kkw][nb + 4] = make_uint4(v[4], v[5], v[6], v[7]);
    };
    auto compute = [&](int buf) {
        #pragma unroll
        for (int ks = 0; ks < 2; ks++) {
            const int k8 = ks * 8;
            uint32_t af[2][4];
            #pragma unroll
            for (int mt = 0; mt < 2; mt++) {
                const int mr = wm * 32 + mt * 16 + g;
                af[mt][0] = As[buf][mr][k8 + t];
                af[mt][1] = As[buf][mr + 8][k8 + t];
                af[mt][2] = As[buf][mr][k8 + t + 4];
                af[mt][3] = As[buf][mr + 8][k8 + t + 4];
            }
            #pragma unroll
            for (int nt = 0; nt < 4; nt++) {
                const int nc = wn * 32 + nt * 8 + g;
                mma16816(acc[0][nt], af[0], Bs[buf][k8 + t][nc], Bs[buf][k8 + t + 4][nc]);
                mma16816(acc[1][nt], af[1], Bs[buf][k8 + t][nc], Bs[buf][k8 + t + 4][nc]);
            }
        }
    };

    const int nk = K / 32;
    loadRegs(0);
    int buf = 0;
    for (int kt = 0; kt < nk; kt++) {
        stsRegs(buf);
        __syncthreads();
        if (kt + 1 < nk) loadRegs((kt + 1) * 32);
        compute(buf);
        buf ^= 1;
    }

    #pragma unroll
    for (int mt = 0; mt < 2; mt++) {
        #pragma unroll
        for (int nt = 0; nt < 4; nt++) {
            const int row = m0 + wm * 32 + mt * 16 + g;
            const int col = wn * 32 + nt * 8 + 2 * t;
            const float b0 = __ldg(bias + col);
            const float b1 = __ldg(bias + col + 1);
            float x0 = acc[mt][nt][0] + b0, x1 = acc[mt][nt][1] + b1;
            float x2 = acc[mt][nt][2] + b0, x3 = acc[mt][nt][3] + b1;
            if (EPI == EPI_ELU) {
                x0 = x0 > 0.f ? x0 : expm1f(x0);
                x1 = x1 > 0.f ? x1 : expm1f(x1);
                x2 = x2 > 0.f ? x2 : expm1f(x2);
                x3 = x3 > 0.f ? x3 : expm1f(x3);
            } else {
                x0 = tanhf(x0); x1 = tanhf(x1);
                x2 = tanhf(x2); x3 = tanhf(x3);
            }
            if (HOUT) {
                __half* Dh = (__half*)Dv;
                *(uint32_t*)&Dh[(long)row       * ldd + dOff + col] = pack2(x0, x1);
                *(uint32_t*)&Dh[(long)(row + 8) * ldd + dOff + col] = pack2(x2, x3);
            } else {
                float* Df = (float*)Dv;
                *(float2*)&Df[(long)row       * ldd + dOff + col] = make_float2(x0, x1);
                *(float2*)&Df[(long)(row + 8) * ldd + dOff + col] = make_float2(x2, x3);
            }
        }
    }
}

__global__ __launch_bounds__(256, 2)
void proj3_kernel(const float* __restrict__ nodes,
                  const float* __restrict__ W_in,   const float* __restrict__ b_in,
                  const float* __restrict__ W_node, const float* __restrict__ b_node,
                  const float* __restrict__ W_out,  const float* __restrict__ b_out,
                  __half* __restrict__ in_rep, __half* __restrict__ out_rep,
                  float* __restrict__ upd)
{
    const int m0 = blockIdx.x * 64;
    const int z  = blockIdx.z;
    if (z == 0)
        gemm_core<EPI_ELU, true >(nodes, 128, W_in,   128, b_in,   in_rep,  128, 0,   128, m0);
    else if (z == 1)
        gemm_core<EPI_ELU, false>(nodes, 128, W_node, 128, b_node, upd,     384, 128, 128, m0);
    else
        gemm_core<EPI_ELU, true >(nodes, 128, W_out,  128, b_out,  out_rep, 128, 0,   128, m0);
}

__global__ __launch_bounds__(256, 2)
void final_kernel(const float* __restrict__ upd, const float* __restrict__ W,
                  const float* __restrict__ b, float* __restrict__ out)
{
    gemm_core<EPI_TANH, false>(upd, 384, W, 384, b, out, 128, 0, 384, blockIdx.x * 64);
}

// ===========================================================================
extern "C" void kernel_launch(void* const* d_in, const int* in_sizes, int n_in,
                              void* d_out, int out_size)
{
    const float* nodes  = (const float*)d_in[0];
    const float* adj    = (const float*)d_in[1];
    const float* W_in   = (const float*)d_in[2];
    const float* b_in   = (const float*)d_in[3];
    const float* W_out  = (const float*)d_in[4];
    const float* b_out  = (const float*)d_in[5];
    const float* W_node = (const float*)d_in[6];
    const float* b_node = (const float*)d_in[7];
    const float* W_upd  = (const float*)d_in[8];
    const float* b_upd  = (const float*)d_in[9];
    float* out = (float*)d_out;

    __half *adjh, *in_rep, *out_rep;
    float *upd;
    cudaGetSymbolAddress((void**)&adjh,    g_adjh);
    cudaGetSymbolAddress((void**)&in_rep,  g_in_rep);
    cudaGetSymbolAddress((void**)&out_rep, g_out_rep);
    cudaGetSymbolAddress((void**)&upd,     g_upd);

    const int SMEM_AGG = 4 * 18944;   // 75776
    cudaFuncSetAttribute(agg_both,
                         cudaFuncAttributeMaxDynamicSharedMemorySize, SMEM_AGG);

    // 1) three ELU projections (small, tensor-bound)
    proj3_kernel<<<dim3(256, 1, 3), 256>>>(nodes, W_in, b_in, W_node, b_node,
                                           W_out, b_out, in_rep, out_rep, upd);

    // 0) adjh = fp16(adj * 4096)  (lean streaming kernel, full occupancy)
    convert_adj<<<8192, 1024>>>(adj, adjh);

    // 2+3) both aggregations, one launch (single wave, 2 CTA/SM)
    agg_both<<<dim3(32, 4, 2), 256, SMEM_AGG>>>(adjh, in_rep, out_rep, upd);

    // 4) out = tanh(upd @ W_upd^T + b_upd)
    final_kernel<<<256, 256>>>(upd, W_upd, b_upd, out);
}

// round 9
// speedup vs baseline: 1.3164x; 1.0493x over previous
#include <cuda_runtime.h>
#include <cuda_fp16.h>
#include <cstdint>
#include <cmath>

// ---------------------------------------------------------------------------
// GraphSageLayer: B=4, N=4096, D_IN=128, REP=128, D_OUT=128
//
//  proj3    : in_rep/out_rep = ELU(nodes@W^T+b) fp16; node_rep->upd fp32
//  agg_both (1 launch, z=2), fp32 adj read directly, cvt in staging:
//     z=0: upd[:,0:128]   = (fp16(adj*4096) @ in_rep)/4096
//     z=1: upd[:,256:384] = (adj^T @ out_rep)  via out_rep^T-major product
//  final    : out = tanh(upd @ W_upd^T + b_upd)
// No adjh scratch pass: adj is converted in-register during SMEM staging.
// ---------------------------------------------------------------------------

__device__ __half g_in_rep [4l * 4096 * 128];
__device__ __half g_out_rep[4l * 4096 * 128];
__device__ float  g_upd    [4l * 4096 * 384];

__device__ __forceinline__ uint32_t pack2(float a, float b) {
    uint32_t r;
    asm("cvt.rn.f16x2.f32 %0, %1, %2;" : "=r"(r) : "f"(b), "f"(a));
    return r;
}
__device__ __forceinline__ void cp16(uint32_t dst, const void* src) {
    asm volatile("cp.async.cg.shared.global [%0], [%1], 16;" :: "r"(dst), "l"(src));
}
__device__ __forceinline__ void cp_commit() {
    asm volatile("cp.async.commit_group;");
}
__device__ __forceinline__ void cp_wait2() {
    asm volatile("cp.async.wait_group 2;");
}
__device__ __forceinline__ void ldsm4(uint32_t* r, uint32_t a) {
    asm volatile("ldmatrix.sync.aligned.m8n8.x4.shared.b16 {%0,%1,%2,%3}, [%4];"
        : "=r"(r[0]), "=r"(r[1]), "=r"(r[2]), "=r"(r[3]) : "r"(a));
}
__device__ __forceinline__ void ldsm4t(uint32_t* r, uint32_t a) {
    asm volatile("ldmatrix.sync.aligned.m8n8.x4.trans.shared.b16 {%0,%1,%2,%3}, [%4];"
        : "=r"(r[0]), "=r"(r[1]), "=r"(r[2]), "=r"(r[3]) : "r"(a));
}
__device__ __forceinline__ void mma16816(float* c, const uint32_t* a,
                                         uint32_t b0, uint32_t b1) {
    asm volatile(
        "mma.sync.aligned.m16n8k16.row.col.f32.f16.f16.f32 "
        "{%0,%1,%2,%3}, {%4,%5,%6,%7}, {%8,%9}, {%0,%1,%2,%3};\n"
        : "+f"(c[0]), "+f"(c[1]), "+f"(c[2]), "+f"(c[3])
        : "r"(a[0]), "r"(a[1]), "r"(a[2]), "r"(a[3]), "r"(b0), "r"(b1));
}

// ===========================================================================
// Aggregation: CTA 128x128, K=4096, BK=32.
//  adj operand: fp32 LDG -> cvt(x4096) -> STS fp16, 2-buffer, reg-prefetched.
//  rep operand: fp16 cp.async, 4-stage.
//  OUTT=false: D[m,v] = sum_k adj[m0+m][k]*4096h * rep[k][v]  -> upd[:,0:128]
//  OUTT=true : D[v,j] = sum_k rep[k][v] * adj[k][n0+j]*4096h  -> upd[:,256:384]^T
// SMEM layout (bytes):
//  in : F(adj) 2 x 128*80 = 20480 @0 ; R(rep) 4 x 8704 @20480   (55296 total)
//  outT: R(rep) 4 x 8704 = 34816 @0 ; F(adj) 2 x 8704 @34816    (52224 total)
//  epilogue transpose buffer (outT): 128*132*4 = 67584 -> alloc 67584
// ===========================================================================
template<bool OUTT>
__device__ __forceinline__ void agg_body(
    const float* __restrict__ adj, const __half* __restrict__ rep,
    float* __restrict__ upd, char* smem)
{
    const int tid  = threadIdx.x;
    const int lane = tid & 31;
    const int warp = tid >> 5;
    const int wm   = warp >> 2;   // 0..1 (m 64 each)
    const int wn   = warp & 3;    // 0..3 (n 32 each)
    const int g    = lane >> 2;
    const int t    = lane & 3;
    const int tile0 = blockIdx.x * 128;   // m0 (in) or n0 (outT)
    const long b   = blockIdx.y;

    const float*  adjB = adj + b * (4096l * 4096);
    const __half* repB = rep + b * (4096l * 128);
    float*        updB = upd + b * (4096l * 384);

    const uint32_t smBase = (uint32_t)__cvta_generic_to_shared(smem);
    // F = fp32-sourced adj tile (2 buffers), R = rep tile (4 cp.async stages)
    const uint32_t sF0 = OUTT ? (smBase + 34816) : smBase;
    const int      FSTRIDE = OUTT ? 8704 : 10240;      // bytes per F buffer
    const uint32_t sR0 = OUTT ? smBase : (smBase + 20480);

    float acc[4][4][4];
    #pragma unroll
    for (int i = 0; i < 4; i++)
        #pragma unroll
        for (int j = 0; j < 4; j++)
            #pragma unroll
            for (int l = 0; l < 4; l++) acc[i][j][l] = 0.f;

    // f32 adj staging indices
    const int f_row = OUTT ? (tid >> 3) : (tid >> 1);   // outT: k row 0..31 ; in: m row 0..127
    const int f_ch  = OUTT ? (tid & 7)  : (tid & 1);    // 16-col chunks
    const float* fSrcBase = OUTT
        ? (adjB + (long)f_row * 4096 + tile0 + f_ch * 16)     // + k0*4096 at call
        : (adjB + (long)(tile0 + f_row) * 4096 + f_ch * 16);  // + k0 at call
    const uint32_t fDst = (OUTT ? f_row * 272 : f_row * 80) + f_ch * 32;

    float4 fv[4];
    auto ldF = [&](int k0) {
        const float* p = OUTT ? (fSrcBase + (long)k0 * 4096) : (fSrcBase + k0);
        #pragma unroll
        for (int i = 0; i < 4; i++) fv[i] = ((const float4*)p)[i];
    };
    auto stsF = [&](int buf) {
        uint32_t w[8];
        #pragma unroll
        for (int i = 0; i < 4; i++) {
            w[2 * i]     = pack2(fv[i].x * 4096.f, fv[i].y * 4096.f);
            w[2 * i + 1] = pack2(fv[i].z * 4096.f, fv[i].w * 4096.f);
        }
        const uint32_t d = sF0 + buf * FSTRIDE + fDst;
        *(uint4*)(smem + (d - smBase))      = make_uint4(w[0], w[1], w[2], w[3]);
        *(uint4*)(smem + (d - smBase) + 16) = make_uint4(w[4], w[5], w[6], w[7]);
    };

    // rep cp.async staging (32 rows x 16 chunks of 16B = 512 chunks, 2/thread)
    const int r_k  = tid >> 4;        // rows r_k, r_k+16
    const int r_nc = tid & 15;
    auto cpR = [&](int st, int k0) {
        const uint32_t sR = sR0 + st * 8704;
        cp16(sR + r_k * 272 + r_nc * 16,        repB + (long)(k0 + r_k) * 128 + r_nc * 8);
        cp16(sR + (r_k + 16) * 272 + r_nc * 16, repB + (long)(k0 + r_k + 16) * 128 + r_nc * 8);
    };

    auto compute = [&](int kt) {
        const uint32_t sA = OUTT ? (sR0 + (kt & 3) * 8704) : (sF0 + (kt & 1) * FSTRIDE);
        const uint32_t sB = OUTT ? (sF0 + (kt & 1) * FSTRIDE) : (sR0 + (kt & 3) * 8704);
        #pragma unroll
        for (int ks = 0; ks < 2; ks++) {
            uint32_t aF[4][4], bF[2][4];
            #pragma unroll
            for (int mt = 0; mt < 4; mt++) {
                if (!OUTT) {
                    ldsm4(aF[mt], sA + (wm * 64 + mt * 16 + (lane & 15)) * 80
                                     + ((lane >> 4) + 2 * ks) * 16);
                } else {
                    ldsm4t(aF[mt], sA + ((lane & 7) + (lane >> 4) * 8 + 16 * ks) * 272
                                      + (wm * 64 + mt * 16 + ((lane >> 3) & 1) * 8) * 2);
                }
            }
            #pragma unroll
            for (int nt = 0; nt < 2; nt++)
                ldsm4t(bF[nt], sB + ((lane & 15) + 16 * ks) * 272
                                  + wn * 64 + nt * 32 + (lane >> 4) * 16);
            #pragma unroll
            for (int mt = 0; mt < 4; mt++)
                #pragma unroll
                for (int n8 = 0; n8 < 4; n8++)
                    mma16816(acc[mt][n8], aF[mt],
                             bF[n8 >> 1][(n8 & 1) * 2], bF[n8 >> 1][(n8 & 1) * 2 + 1]);
        }
    };

    // prologue
    ldF(0);
    #pragma unroll
    for (int s = 0; s < 3; s++) { cpR(s, s * 32); cp_commit(); }

    #pragma unroll 1
    for (int kt = 0; kt < 128; kt++) {
        stsF(kt & 1);
        cp_wait2();
        __syncthreads();
        if (kt + 1 < 128) ldF((kt + 1) * 32);
        const int nx = kt + 3;
        if (nx < 128) cpR(nx & 3, nx * 32);
        cp_commit();
        compute(kt);
    }

    const float s = 1.f / 4096.f;
    if (!OUTT) {
        #pragma unroll
        for (int mt = 0; mt < 4; mt++)
            #pragma unroll
            for (int n8 = 0; n8 < 4; n8++) {
                const int row = tile0 + wm * 64 + mt * 16 + g;
                const int col = wn * 32 + n8 * 8 + 2 * t;
                *(float2*)&updB[(long)row * 384 + col] =
                    make_float2(acc[mt][n8][0] * s, acc[mt][n8][1] * s);
                *(float2*)&updB[(long)(row + 8) * 384 + col] =
                    make_float2(acc[mt][n8][2] * s, acc[mt][n8][3] * s);
            }
    } else {
        __syncthreads();
        float* fsm = (float*)smem;   // [v][132] = 67584 B
        #pragma unroll
        for (int mt = 0; mt < 4; mt++)
            #pragma unroll
            for (int n8 = 0; n8 < 4; n8++) {
                const int v = wm * 64 + mt * 16 + g;
                const int j = wn * 32 + n8 * 8 + 2 * t;
                fsm[v * 132 + j]           = acc[mt][n8][0] * s;
                fsm[v * 132 + j + 1]       = acc[mt][n8][1] * s;
                fsm[(v + 8) * 132 + j]     = acc[mt][n8][2] * s;
                fsm[(v + 8) * 132 + j + 1] = acc[mt][n8][3] * s;
            }
        __syncthreads();
        const int j  = tid >> 1;
        const int vb = (tid & 1) * 64;
        float* dst = &updB[(long)(tile0 + j) * 384 + 256 + vb];
        #pragma unroll
        for (int i = 0; i < 16; i++) {
            const int v = vb + i * 4;
            ((float4*)dst)[i] = make_float4(
                fsm[v * 132 + j],       fsm[(v + 1) * 132 + j],
                fsm[(v + 2) * 132 + j], fsm[(v + 3) * 132 + j]);
        }
    }
}

__global__ __launch_bounds__(256, 2)
void agg_both(const float* __restrict__ adj,
              const __half* __restrict__ in_rep,
              const __half* __restrict__ out_rep,
              float* __restrict__ upd)
{
    extern __shared__ char smem[];
    if (blockIdx.z == 0) agg_body<false>(adj, in_rep,  upd, smem);
    else                 agg_body<true >(adj, out_rep, upd, smem);
}

// ===========================================================================
// mma.sync fp16 GEMM for proj / final (small K): CTA 64x128, BK=32.
// ===========================================================================
#define AROW 20
#define BROW 136
enum { EPI_ELU = 1, EPI_TANH = 2 };

template<int EPI, bool HOUT>
__device__ __forceinline__ void gemm_core(
    const float* __restrict__ Af, int lda,
    const float* __restrict__ Bf, int ldb,     // B: NxK row-major (TN)
    const float* __restrict__ bias,
    void* __restrict__ Dv, int ldd, int dOff,
    int K, int m0)
{
    __shared__ uint32_t As[2][64][AROW];
    __shared__ uint32_t Bs[2][16][BROW];

    const int tid  = threadIdx.x;
    const int lane = tid & 31;
    const int warp = tid >> 5;
    const int wm   = warp >> 2;
    const int wn   = warp & 3;
    const int g    = lane >> 2;
    const int t    = lane & 3;

    float acc[2][4][4];
    #pragma unroll
    for (int i = 0; i < 2; i++)
        #pragma unroll
        for (int j = 0; j < 4; j++)
            #pragma unroll
            for (int l = 0; l < 4; l++) acc[i][j][l] = 0.f;

    const int m_a = tid >> 2, q_a = tid & 3;
    const int kkw = tid & 15, nb = (tid >> 4) * 8;

    float fa[8];
    float2 rbf[8];

    auto loadRegs = [&](int k0) {
        const float4* p = (const float4*)(Af + (long)(m0 + m_a) * lda + k0 + 8 * q_a);
        float4 v0 = p[0], v1 = p[1];
        fa[0] = v0.x; fa[1] = v0.y; fa[2] = v0.z; fa[3] = v0.w;
        fa[4] = v1.x; fa[5] = v1.y; fa[6] = v1.z; fa[7] = v1.w;
        #pragma unroll
        for (int i = 0; i < 8; i++)
            rbf[i] = *(const float2*)(Bf + (long)(nb + i) * ldb + k0 + 2 * kkw);
    };
    auto stsRegs = [&](int buf) {
        uint32_t w[4];
        #pragma unroll
        for (int i = 0; i < 4; i++) w[i] = pack2(fa[2 * i], fa[2 * i + 1]);
        *(uint4*)&As[buf][m_a][4 * q_a] = make_uint4(w[0], w[1], w[2], w[3]);
        uint32_t v[8];
        #pragma unroll
        for (int i = 0; i < 8; i++) v[i] = pack2(rbf[i].x, rbf[i].y);
        *(uint4*)&Bs[buf][kkw][nb]     = make_uint4(v[0], v[1], v[2], v[3]);
        *(uint4*)&Bs[buf][kkw][nb + 4] = make_uint4(v[4], v[5], v[6], v[7]);
    };
    auto compute = [&](int buf) {
        #pragma unroll
        for (int ks = 0; ks < 2; ks++) {
            const int k8 = ks * 8;
            uint32_t af[2][4];
            #pragma unroll
            for (int mt = 0; mt < 2; mt++) {
                const int mr = wm * 32 + mt * 16 + g;
                af[mt][0] = As[buf][mr][k8 + t];
                af[mt][1] = As[buf][mr + 8][k8 + t];
                af[mt][2] = As[buf][mr][k8 + t + 4];
                af[mt][3] = As[buf][mr + 8][k8 + t + 4];
            }
            #pragma unroll
            for (int nt = 0; nt < 4; nt++) {
                const int nc = wn * 32 + nt * 8 + g;
                mma16816(acc[0][nt], af[0], Bs[buf][k8 + t][nc], Bs[buf][k8 + t + 4][nc]);
                mma16816(acc[1][nt], af[1], Bs[buf][k8 + t][nc], Bs[buf][k8 + t + 4][nc]);
            }
        }
    };

    const int nk = K / 32;
    loadRegs(0);
    int buf = 0;
    for (int kt = 0; kt < nk; kt++) {
        stsRegs(buf);
        __syncthreads();
        if (kt + 1 < nk) loadRegs((kt + 1) * 32);
        compute(buf);
        buf ^= 1;
    }

    #pragma unroll
    for (int mt = 0; mt < 2; mt++) {
        #pragma unroll
        for (int nt = 0; nt < 4; nt++) {
            const int row = m0 + wm * 32 + mt * 16 + g;
            const int col = wn * 32 + nt * 8 + 2 * t;
            const float b0 = __ldg(bias + col);
            const float b1 = __ldg(bias + col + 1);
            float x0 = acc[mt][nt][0] + b0, x1 = acc[mt][nt][1] + b1;
            float x2 = acc[mt][nt][2] + b0, x3 = acc[mt][nt][3] + b1;
            if (EPI == EPI_ELU) {
                x0 = x0 > 0.f ? x0 : expm1f(x0);
                x1 = x1 > 0.f ? x1 : expm1f(x1);
                x2 = x2 > 0.f ? x2 : expm1f(x2);
                x3 = x3 > 0.f ? x3 : expm1f(x3);
            } else {
                x0 = tanhf(x0); x1 = tanhf(x1);
                x2 = tanhf(x2); x3 = tanhf(x3);
            }
            if (HOUT) {
                __half* Dh = (__half*)Dv;
                *(uint32_t*)&Dh[(long)row       * ldd + dOff + col] = pack2(x0, x1);
                *(uint32_t*)&Dh[(long)(row + 8) * ldd + dOff + col] = pack2(x2, x3);
            } else {
                float* Df = (float*)Dv;
                *(float2*)&Df[(long)row       * ldd + dOff + col] = make_float2(x0, x1);
                *(float2*)&Df[(long)(row + 8) * ldd + dOff + col] = make_float2(x2, x3);
            }
        }
    }
}

__global__ __launch_bounds__(256, 2)
void proj3_kernel(const float* __restrict__ nodes,
                  const float* __restrict__ W_in,   const float* __restrict__ b_in,
                  const float* __restrict__ W_node, const float* __restrict__ b_node,
                  const float* __restrict__ W_out,  const float* __restrict__ b_out,
                  __half* __restrict__ in_rep, __half* __restrict__ out_rep,
                  float* __restrict__ upd)
{
    const int m0 = blockIdx.x * 64;
    const int z  = blockIdx.z;
    if (z == 0)
        gemm_core<EPI_ELU, true >(nodes, 128, W_in,   128, b_in,   in_rep,  128, 0,   128, m0);
    else if (z == 1)
        gemm_core<EPI_ELU, false>(nodes, 128, W_node, 128, b_node, upd,     384, 128, 128, m0);
    else
        gemm_core<EPI_ELU, true >(nodes, 128, W_out,  128, b_out,  out_rep, 128, 0,   128, m0);
}

__global__ __launch_bounds__(256, 2)
void final_kernel(const float* __restrict__ upd, const float* __restrict__ W,
                  const float* __restrict__ b, float* __restrict__ out)
{
    gemm_core<EPI_TANH, false>(upd, 384, W, 384, b, out, 128, 0, 384, blockIdx.x * 64);
}

// ===========================================================================
extern "C" void kernel_launch(void* const* d_in, const int* in_sizes, int n_in,
                              void* d_out, int out_size)
{
    const float* nodes  = (const float*)d_in[0];
    const float* adj    = (const float*)d_in[1];
    const float* W_in   = (const float*)d_in[2];
    const float* b_in   = (const float*)d_in[3];
    const float* W_out  = (const float*)d_in[4];
    const float* b_out  = (const float*)d_in[5];
    const float* W_node = (const float*)d_in[6];
    const float* b_node = (const float*)d_in[7];
    const float* W_upd  = (const float*)d_in[8];
    const float* b_upd  = (const float*)d_in[9];
    float* out = (float*)d_out;

    __half *in_rep, *out_rep;
    float *upd;
    cudaGetSymbolAddress((void**)&in_rep,  g_in_rep);
    cudaGetSymbolAddress((void**)&out_rep, g_out_rep);
    cudaGetSymbolAddress((void**)&upd,     g_upd);

    const int SMEM_AGG = 128 * 132 * 4;   // 67584 (covers both mainloop layouts)
    cudaFuncSetAttribute(agg_both,
                         cudaFuncAttributeMaxDynamicSharedMemorySize, SMEM_AGG);

    // 1) three ELU projections
    proj3_kernel<<<dim3(256, 1, 3), 256>>>(nodes, W_in, b_in, W_node, b_node,
                                           W_out, b_out, in_rep, out_rep, upd);

    // 2+3) both aggregations, one launch, fp32 adj read directly
    agg_both<<<dim3(32, 4, 2), 256, SMEM_AGG>>>(adj, in_rep, out_rep, upd);

    // 4) out = tanh(upd @ W_upd^T + b_upd)
    final_kernel<<<256, 256>>>(upd, W_upd, b_upd, out);
}